// round 1
// baseline (speedup 1.0000x reference)
#include <cuda_runtime.h>
#include <float.h>

#define BB 4
#define NN 4096
#define DIMD 512
#define HH 8
#define DH 64
#define MM 256
#define LL 16
#define BH (BB*HH)          // 32
#define ROWS_TOT (BB*NN)    // 16384

// ------------------- scratch (device globals; no allocs) -------------------
__device__ float g_q[BH*NN*DH];
__device__ float g_k[BH*NN*DH];
__device__ float g_v[BH*NN*DH];
__device__ float g_ql[BH*MM*DH];
__device__ float g_kl[BH*MM*DH];
__device__ float g_attn1[(size_t)BH*NN*MM];
__device__ float g_attn3[(size_t)BH*MM*NN];
__device__ float g_attn2[BH*MM*MM];
__device__ float g_zA[BH*MM*MM];
__device__ float g_zB[BH*MM*MM];
__device__ float g_xz[BH*MM*MM];
__device__ float g_t[BH*MM*MM];
__device__ float g_u[BH*MM*MM];
__device__ float g_tmp1[BH*MM*DH];
__device__ float g_tmp2[BH*MM*DH];
__device__ float g_outh[BH*NN*DH];
__device__ int   g_red[2];

// ------------------- kernel 1: qkv = x @ w_qkv, scatter to heads ----------
__global__ void k_qkv(const float* __restrict__ X, const float* __restrict__ W,
                      float* __restrict__ q, float* __restrict__ k, float* __restrict__ v)
{
    __shared__ float As[64][16];
    __shared__ float Bs[16][64];
    int tid = threadIdx.x;
    int row0 = blockIdx.y * 64, col0 = blockIdx.x * 64;
    int tx = tid & 15, ty = tid >> 4;
    float acc[4][4] = {};
    for (int k0 = 0; k0 < DIMD; k0 += 16) {
        for (int i = tid; i < 1024; i += 256) {
            int r = i >> 4, kk = i & 15;
            As[r][kk] = X[(size_t)(row0 + r) * DIMD + k0 + kk];
        }
        for (int i = tid; i < 1024; i += 256) {
            int kk = i >> 6, c = i & 63;
            Bs[kk][c] = W[(size_t)(k0 + kk) * (3 * DIMD) + col0 + c];
        }
        __syncthreads();
#pragma unroll
        for (int kk = 0; kk < 16; kk++) {
            float a_[4];
#pragma unroll
            for (int i = 0; i < 4; i++) a_[i] = As[ty * 4 + i][kk];
            float4 bb = *(const float4*)&Bs[kk][tx * 4];
            float b_[4] = {bb.x, bb.y, bb.z, bb.w};
#pragma unroll
            for (int i = 0; i < 4; i++)
#pragma unroll
                for (int j = 0; j < 4; j++) acc[i][j] += a_[i] * b_[j];
        }
        __syncthreads();
    }
#pragma unroll
    for (int i = 0; i < 4; i++) {
        int rg = row0 + ty * 4 + i;
        int b = rg >> 12, n = rg & 4095;
#pragma unroll
        for (int j = 0; j < 4; j++) {
            int cg = col0 + tx * 4 + j;
            int which = cg >> 9;
            int hc = cg & 511;
            int h = hc >> 6, d = hc & 63;
            size_t o = ((size_t)(b * HH + h) * NN + n) * DH + d;
            float val = acc[i][j];
            if (which == 0) q[o] = val * 0.125f;
            else if (which == 1) k[o] = val;
            else v[o] = val;
        }
    }
}

// ------------------- kernel 2: landmark means -----------------------------
__global__ void k_land(const float* __restrict__ q, const float* __restrict__ k,
                       float* __restrict__ ql, float* __restrict__ kl)
{
    int idx = blockIdx.x * 256 + threadIdx.x;   // [bh][m][d]
    int d = idx & 63;
    int m = (idx >> 6) & 255;
    int bh = idx >> 14;
    size_t base = ((size_t)bh * NN + m * LL) * DH + d;
    float sq = 0.f, sk = 0.f;
#pragma unroll
    for (int i = 0; i < LL; i++) { sq += q[base + (size_t)i * DH]; sk += k[base + (size_t)i * DH]; }
    ql[idx] = sq * (1.f / LL);
    kl[idx] = sk * (1.f / LL);
}

// ------- kernel 3: sim (Q rows x 256 landmarks) + row softmax, fused ------
__global__ void k_sim_softmax(const float* __restrict__ Q, const float* __restrict__ KL,
                              float* __restrict__ Out, int nrows)
{
    extern __shared__ float sm[];
    float* ks = sm;                 // [256][65]
    float* qs = sm + 256 * 65;      // [64][65]
    int tid = threadIdx.x;
    int bh = blockIdx.y;
    int row0 = blockIdx.x * 64;
    const float* Qb = Q + ((size_t)bh * nrows + row0) * DH;
    const float* Kb = KL + (size_t)bh * MM * DH;
    for (int i = tid; i < 256 * 64; i += 256) { int c = i >> 6, d = i & 63; ks[c * 65 + d] = Kb[i]; }
    for (int i = tid; i < 64 * 64;  i += 256) { int r = i >> 6, d = i & 63; qs[r * 65 + d] = Qb[i]; }
    __syncthreads();
    int tx = tid & 31, ty = tid >> 5;
    int c1 = tx * 4, c2 = 128 + tx * 4;
    float acc[8][8] = {};
#pragma unroll 4
    for (int d = 0; d < 64; d++) {
        float a_[8];
#pragma unroll
        for (int i = 0; i < 8; i++) a_[i] = qs[(ty * 8 + i) * 65 + d];
        float b_[8];
#pragma unroll
        for (int j = 0; j < 4; j++) { b_[j] = ks[(c1 + j) * 65 + d]; b_[4 + j] = ks[(c2 + j) * 65 + d]; }
#pragma unroll
        for (int i = 0; i < 8; i++)
#pragma unroll
            for (int j = 0; j < 8; j++) acc[i][j] += a_[i] * b_[j];
    }
#pragma unroll
    for (int i = 0; i < 8; i++) {
        float m = acc[i][0];
#pragma unroll
        for (int j = 1; j < 8; j++) m = fmaxf(m, acc[i][j]);
        for (int o = 16; o > 0; o >>= 1) m = fmaxf(m, __shfl_xor_sync(0xffffffffu, m, o));
        float s = 0.f;
#pragma unroll
        for (int j = 0; j < 8; j++) { float e = expf(acc[i][j] - m); acc[i][j] = e; s += e; }
        for (int o = 16; o > 0; o >>= 1) s += __shfl_xor_sync(0xffffffffu, s, o);
        float inv = 1.f / s;
        float* orow = Out + ((size_t)bh * nrows + row0 + ty * 8 + i) * MM;
        float4 w1 = {acc[i][0] * inv, acc[i][1] * inv, acc[i][2] * inv, acc[i][3] * inv};
        float4 w2 = {acc[i][4] * inv, acc[i][5] * inv, acc[i][6] * inv, acc[i][7] * inv};
        *(float4*)(orow + c1) = w1;
        *(float4*)(orow + c2) = w2;
    }
}

// -------- kernel 5a: sim3 raw = ql @ k^T tiles (no softmax) ---------------
__global__ void k_sim3(const float* __restrict__ QL, const float* __restrict__ K,
                       float* __restrict__ Out)
{
    extern __shared__ float sm[];
    float* ks = sm;                 // [256][65] token tile
    float* qs = sm + 256 * 65;      // [64][65]
    int tid = threadIdx.x;
    int bh = blockIdx.z;
    int row0 = blockIdx.y * 64;     // landmarks
    int col0 = blockIdx.x * 256;    // tokens
    const float* Qb = QL + ((size_t)bh * MM + row0) * DH;
    const float* Kb = K + ((size_t)bh * NN + col0) * DH;
    for (int i = tid; i < 256 * 64; i += 256) { int c = i >> 6, d = i & 63; ks[c * 65 + d] = Kb[i]; }
    for (int i = tid; i < 64 * 64;  i += 256) { int r = i >> 6, d = i & 63; qs[r * 65 + d] = Qb[i]; }
    __syncthreads();
    int tx = tid & 31, ty = tid >> 5;
    int c1 = tx * 4, c2 = 128 + tx * 4;
    float acc[8][8] = {};
#pragma unroll 4
    for (int d = 0; d < 64; d++) {
        float a_[8];
#pragma unroll
        for (int i = 0; i < 8; i++) a_[i] = qs[(ty * 8 + i) * 65 + d];
        float b_[8];
#pragma unroll
        for (int j = 0; j < 4; j++) { b_[j] = ks[(c1 + j) * 65 + d]; b_[4 + j] = ks[(c2 + j) * 65 + d]; }
#pragma unroll
        for (int i = 0; i < 8; i++)
#pragma unroll
            for (int j = 0; j < 8; j++) acc[i][j] += a_[i] * b_[j];
    }
#pragma unroll
    for (int i = 0; i < 8; i++) {
        float* orow = Out + ((size_t)bh * MM + row0 + ty * 8 + i) * NN + col0;
        float4 w1 = {acc[i][0], acc[i][1], acc[i][2], acc[i][3]};
        float4 w2 = {acc[i][4], acc[i][5], acc[i][6], acc[i][7]};
        *(float4*)(orow + c1) = w1;
        *(float4*)(orow + c2) = w2;
    }
}

// -------- kernel 5b: softmax over rows of length 4096 ---------------------
__global__ void k_softmax4096(float* __restrict__ A)
{
    __shared__ float smax[32];
    __shared__ float ssum[32];
    int tid = threadIdx.x;
    int wid = tid >> 5, lane = tid & 31;
    float4* row = (float4*)(A + ((size_t)blockIdx.y * MM + blockIdx.x) * NN);
    float4 vals[4];
    float m = -FLT_MAX;
#pragma unroll
    for (int kk = 0; kk < 4; kk++) {
        vals[kk] = row[tid + 256 * kk];
        m = fmaxf(m, fmaxf(fmaxf(vals[kk].x, vals[kk].y), fmaxf(vals[kk].z, vals[kk].w)));
    }
    for (int o = 16; o > 0; o >>= 1) m = fmaxf(m, __shfl_xor_sync(0xffffffffu, m, o));
    if (lane == 0) smax[wid] = m;
    __syncthreads();
    if (wid == 0) {
        float v = (lane < 8) ? smax[lane] : -FLT_MAX;
        for (int o = 16; o > 0; o >>= 1) v = fmaxf(v, __shfl_xor_sync(0xffffffffu, v, o));
        if (lane == 0) smax[0] = v;
    }
    __syncthreads();
    m = smax[0];
    float s = 0.f;
#pragma unroll
    for (int kk = 0; kk < 4; kk++) {
        vals[kk].x = expf(vals[kk].x - m); vals[kk].y = expf(vals[kk].y - m);
        vals[kk].z = expf(vals[kk].z - m); vals[kk].w = expf(vals[kk].w - m);
        s += vals[kk].x + vals[kk].y + vals[kk].z + vals[kk].w;
    }
    for (int o = 16; o > 0; o >>= 1) s += __shfl_xor_sync(0xffffffffu, s, o);
    if (lane == 0) ssum[wid] = s;
    __syncthreads();
    if (wid == 0) {
        float v = (lane < 8) ? ssum[lane] : 0.f;
        for (int o = 16; o > 0; o >>= 1) v += __shfl_xor_sync(0xffffffffu, v, o);
        if (lane == 0) ssum[0] = v;
    }
    __syncthreads();
    float inv = 1.f / ssum[0];
#pragma unroll
    for (int kk = 0; kk < 4; kk++) {
        vals[kk].x *= inv; vals[kk].y *= inv; vals[kk].z *= inv; vals[kk].w *= inv;
        row[tid + 256 * kk] = vals[kk];
    }
}

// -------- pinv prep: global max of row-sums and col-sums ------------------
__global__ void k_zero_red(int* red) { red[0] = 0; red[1] = 0; }

__global__ void k_pinv_prep(const float* __restrict__ X, int* red)
{
    __shared__ float s1[32], s2[32];
    int bh = blockIdx.x;
    int j = threadIdx.x;
    int wid = j >> 5, lane = j & 31;
    const float* Xb = X + (size_t)bh * MM * MM;
    float cs = 0.f, rs = 0.f;
    for (int i = 0; i < MM; i++) { cs += fabsf(Xb[j * MM + i]); rs += fabsf(Xb[i * MM + j]); }
    for (int o = 16; o > 0; o >>= 1) {
        cs = fmaxf(cs, __shfl_xor_sync(0xffffffffu, cs, o));
        rs = fmaxf(rs, __shfl_xor_sync(0xffffffffu, rs, o));
    }
    if (lane == 0) { s1[wid] = cs; s2[wid] = rs; }
    __syncthreads();
    if (wid == 0) {
        float a = (lane < 8) ? s1[lane] : 0.f;
        float b = (lane < 8) ? s2[lane] : 0.f;
        for (int o = 16; o > 0; o >>= 1) {
            a = fmaxf(a, __shfl_xor_sync(0xffffffffu, a, o));
            b = fmaxf(b, __shfl_xor_sync(0xffffffffu, b, o));
        }
        if (lane == 0) {
            atomicMax(&red[0], __float_as_int(a));
            atomicMax(&red[1], __float_as_int(b));
        }
    }
}

__global__ void k_zinit(const float* __restrict__ X, float* __restrict__ Z, const int* red)
{
    float denom = __int_as_float(red[0]) * __int_as_float(red[1]) + 1e-8f;
    int idx = blockIdx.x * 256 + threadIdx.x;  // [bh][i][j]
    int bh = idx >> 16;
    int rem = idx & 65535;
    int i = rem >> 8, j = rem & 255;
    Z[idx] = X[((size_t)bh << 16) + j * MM + i] / denom;
}

// -------- batched 256x256x256 gemm: C = scale*(coef*A + sgn*A@B) ---------
__global__ void k_gemm256(const float* __restrict__ A, const float* __restrict__ B,
                          float* __restrict__ C, float coef, float sgn, float scale)
{
    __shared__ float As[64][16];
    __shared__ float Bs[16][64];
    int tid = threadIdx.x;
    size_t base = (size_t)blockIdx.z << 16;
    int row0 = blockIdx.y * 64, col0 = blockIdx.x * 64;
    int tx = tid & 15, ty = tid >> 4;
    float acc[4][4] = {};
    for (int k0 = 0; k0 < MM; k0 += 16) {
        for (int i = tid; i < 1024; i += 256) {
            int r = i >> 4, kk = i & 15;
            As[r][kk] = A[base + (size_t)(row0 + r) * MM + k0 + kk];
        }
        for (int i = tid; i < 1024; i += 256) {
            int kk = i >> 6, c = i & 63;
            Bs[kk][c] = B[base + (size_t)(k0 + kk) * MM + col0 + c];
        }
        __syncthreads();
#pragma unroll
        for (int kk = 0; kk < 16; kk++) {
            float a_[4];
#pragma unroll
            for (int i = 0; i < 4; i++) a_[i] = As[ty * 4 + i][kk];
            float4 bb = *(const float4*)&Bs[kk][tx * 4];
            float b_[4] = {bb.x, bb.y, bb.z, bb.w};
#pragma unroll
            for (int i = 0; i < 4; i++)
#pragma unroll
                for (int j = 0; j < 4; j++) acc[i][j] += a_[i] * b_[j];
        }
        __syncthreads();
    }
#pragma unroll
    for (int i = 0; i < 4; i++) {
        int rg = row0 + ty * 4 + i;
#pragma unroll
        for (int j = 0; j < 4; j++) {
            int cg = col0 + tx * 4 + j;
            float e = sgn * acc[i][j];
            if (coef != 0.f) e += coef * A[base + (size_t)rg * MM + cg];
            C[base + (size_t)rg * MM + cg] = scale * e;
        }
    }
}

// -------- batched [rows x 64] gemm, K variable ----------------------------
__global__ void k_gemm_b64(const float* __restrict__ A, size_t sA, int lda,
                           const float* __restrict__ B, size_t sB,
                           float* __restrict__ C, size_t sC, int K)
{
    __shared__ float As[64][16];
    __shared__ float Bs[16][64];
    int tid = threadIdx.x;
    int bh = blockIdx.y;
    int row0 = blockIdx.x * 64;
    const float* Ab = A + (size_t)bh * sA;
    const float* Bb = B + (size_t)bh * sB;
    float* Cb = C + (size_t)bh * sC;
    int tx = tid & 15, ty = tid >> 4;
    float acc[4][4] = {};
    for (int k0 = 0; k0 < K; k0 += 16) {
        for (int i = tid; i < 1024; i += 256) {
            int r = i >> 4, kk = i & 15;
            As[r][kk] = Ab[(size_t)(row0 + r) * lda + k0 + kk];
        }
        for (int i = tid; i < 1024; i += 256) {
            int kk = i >> 6, c = i & 63;
            Bs[kk][c] = Bb[(size_t)(k0 + kk) * 64 + c];
        }
        __syncthreads();
#pragma unroll
        for (int kk = 0; kk < 16; kk++) {
            float a_[4];
#pragma unroll
            for (int i = 0; i < 4; i++) a_[i] = As[ty * 4 + i][kk];
            float4 bb = *(const float4*)&Bs[kk][tx * 4];
            float b_[4] = {bb.x, bb.y, bb.z, bb.w};
#pragma unroll
            for (int i = 0; i < 4; i++)
#pragma unroll
                for (int j = 0; j < 4; j++) acc[i][j] += a_[i] * b_[j];
        }
        __syncthreads();
    }
#pragma unroll
    for (int i = 0; i < 4; i++) {
        float4 st = {acc[i][0], acc[i][1], acc[i][2], acc[i][3]};
        *(float4*)&Cb[(size_t)(row0 + ty * 4 + i) * 64 + tx * 4] = st;
    }
}

// -------- outh = attn1 @ tmp2 + depthwise-conv(v) residual ---------------
__global__ void k_outh(const float* __restrict__ attn1, const float* __restrict__ tmp2,
                       const float* __restrict__ v, const float* __restrict__ wres,
                       float* __restrict__ outh)
{
    __shared__ float As[64][16];
    __shared__ float Bs[16][64];
    __shared__ __align__(16) float vbuf[96 * 64];
    __shared__ float wc[33];
    int tid = threadIdx.x;
    int bh = blockIdx.y;
    int h = bh & 7;
    int row0 = blockIdx.x * 64;
    const float* Ab = attn1 + (size_t)bh * NN * MM;
    const float* Bb = tmp2 + (size_t)bh * MM * DH;
    int tx = tid & 15, ty = tid >> 4;
    float acc[4][4] = {};
    for (int k0 = 0; k0 < MM; k0 += 16) {
        for (int i = tid; i < 1024; i += 256) {
            int r = i >> 4, kk = i & 15;
            As[r][kk] = Ab[(size_t)(row0 + r) * MM + k0 + kk];
        }
        for (int i = tid; i < 1024; i += 256) {
            int kk = i >> 6, c = i & 63;
            Bs[kk][c] = Bb[(size_t)(k0 + kk) * 64 + c];
        }
        __syncthreads();
#pragma unroll
        for (int kk = 0; kk < 16; kk++) {
            float a_[4];
#pragma unroll
            for (int i = 0; i < 4; i++) a_[i] = As[ty * 4 + i][kk];
            float4 bb = *(const float4*)&Bs[kk][tx * 4];
            float b_[4] = {bb.x, bb.y, bb.z, bb.w};
#pragma unroll
            for (int i = 0; i < 4; i++)
#pragma unroll
                for (int j = 0; j < 4; j++) acc[i][j] += a_[i] * b_[j];
        }
        __syncthreads();
    }
    // conv residual tile
    if (tid < 33) wc[tid] = wres[h * 33 + tid];
    for (int i = tid; i < 96 * 64; i += 256) {
        int rr = i >> 6, d = i & 63;
        int n = row0 + rr - 16;
        vbuf[i] = (n >= 0 && n < NN) ? v[((size_t)bh * NN + n) * DH + d] : 0.f;
    }
    __syncthreads();
#pragma unroll
    for (int i = 0; i < 4; i++) {
        int rl = ty * 4 + i;
        float4 cv = {0.f, 0.f, 0.f, 0.f};
#pragma unroll 1
        for (int t = 0; t < 33; t++) {
            float w = wc[t];
            float4 vb = *(const float4*)&vbuf[(rl + t) * 64 + tx * 4];
            cv.x += w * vb.x; cv.y += w * vb.y; cv.z += w * vb.z; cv.w += w * vb.w;
        }
        float4 st = {acc[i][0] + cv.x, acc[i][1] + cv.y, acc[i][2] + cv.z, acc[i][3] + cv.w};
        *(float4*)&outh[((size_t)bh * NN + row0 + rl) * DH + tx * 4] = st;
    }
}

// -------- final: out = reshape(outh) @ w_out ------------------------------
__global__ void k_final(const float* __restrict__ outh, const float* __restrict__ W,
                        float* __restrict__ out)
{
    __shared__ float As[64][16];
    __shared__ float Bs[16][64];
    int tid = threadIdx.x;
    int row0 = blockIdx.y * 64, col0 = blockIdx.x * 64;
    int tx = tid & 15, ty = tid >> 4;
    float acc[4][4] = {};
    for (int k0 = 0; k0 < DIMD; k0 += 16) {
        for (int i = tid; i < 1024; i += 256) {
            int r = i >> 4, kk = i & 15;
            int rg = row0 + r, kg = k0 + kk;
            int b = rg >> 12, n = rg & 4095;
            int h = kg >> 6, d = kg & 63;
            As[r][kk] = outh[((size_t)(b * HH + h) * NN + n) * DH + d];
        }
        for (int i = tid; i < 1024; i += 256) {
            int kk = i >> 6, c = i & 63;
            Bs[kk][c] = W[(size_t)(k0 + kk) * DIMD + col0 + c];
        }
        __syncthreads();
#pragma unroll
        for (int kk = 0; kk < 16; kk++) {
            float a_[4];
#pragma unroll
            for (int i = 0; i < 4; i++) a_[i] = As[ty * 4 + i][kk];
            float4 bb = *(const float4*)&Bs[kk][tx * 4];
            float b_[4] = {bb.x, bb.y, bb.z, bb.w};
#pragma unroll
            for (int i = 0; i < 4; i++)
#pragma unroll
                for (int j = 0; j < 4; j++) acc[i][j] += a_[i] * b_[j];
        }
        __syncthreads();
    }
#pragma unroll
    for (int i = 0; i < 4; i++) {
        int rg = row0 + ty * 4 + i;
        float4 st = {acc[i][0], acc[i][1], acc[i][2], acc[i][3]};
        *(float4*)&out[(size_t)rg * DIMD + col0 + tx * 4] = st;
    }
}

// --------------------------- host launcher --------------------------------
extern "C" void kernel_launch(void* const* d_in, const int* in_sizes, int n_in,
                              void* d_out, int out_size)
{
    const float *x = nullptr, *wqkv = nullptr, *wout = nullptr, *wres = nullptr;
    for (int i = 0; i < n_in; i++) {
        switch (in_sizes[i]) {
            case 8388608: x = (const float*)d_in[i]; break;
            case 786432:  wqkv = (const float*)d_in[i]; break;
            case 262144:  wout = (const float*)d_in[i]; break;
            case 264:     wres = (const float*)d_in[i]; break;
            default: break;
        }
    }

    float *pq, *pk, *pv, *pql, *pkl, *pattn1, *pattn3, *pattn2;
    float *pzA, *pzB, *pxz, *pt, *pu, *ptmp1, *ptmp2, *pouth;
    int* pred;
    cudaGetSymbolAddress((void**)&pq, g_q);
    cudaGetSymbolAddress((void**)&pk, g_k);
    cudaGetSymbolAddress((void**)&pv, g_v);
    cudaGetSymbolAddress((void**)&pql, g_ql);
    cudaGetSymbolAddress((void**)&pkl, g_kl);
    cudaGetSymbolAddress((void**)&pattn1, g_attn1);
    cudaGetSymbolAddress((void**)&pattn3, g_attn3);
    cudaGetSymbolAddress((void**)&pattn2, g_attn2);
    cudaGetSymbolAddress((void**)&pzA, g_zA);
    cudaGetSymbolAddress((void**)&pzB, g_zB);
    cudaGetSymbolAddress((void**)&pxz, g_xz);
    cudaGetSymbolAddress((void**)&pt, g_t);
    cudaGetSymbolAddress((void**)&pu, g_u);
    cudaGetSymbolAddress((void**)&ptmp1, g_tmp1);
    cudaGetSymbolAddress((void**)&ptmp2, g_tmp2);
    cudaGetSymbolAddress((void**)&pouth, g_outh);
    cudaGetSymbolAddress((void**)&pred, g_red);

    size_t shmem = (size_t)(256 + 64) * 65 * sizeof(float);  // 83200 B
    cudaFuncSetAttribute(k_sim_softmax, cudaFuncAttributeMaxDynamicSharedMemorySize, (int)shmem);
    cudaFuncSetAttribute(k_sim3, cudaFuncAttributeMaxDynamicSharedMemorySize, (int)shmem);

    // 1) qkv projection + head scatter (q scaled)
    k_qkv<<<dim3(24, 256), 256>>>(x, wqkv, pq, pk, pv);
    // 2) landmarks
    k_land<<<2048, 256>>>(pq, pk, pql, pkl);
    // 3) sim1 + softmax : [bh,4096,256]
    k_sim_softmax<<<dim3(64, BH), 256, shmem>>>(pq, pkl, pattn1, NN);
    // 4) sim2 + softmax : [bh,256,256]
    k_sim_softmax<<<dim3(4, BH), 256, shmem>>>(pql, pkl, pattn2, MM);
    // 5) sim3 raw + softmax over 4096
    k_sim3<<<dim3(16, 4, BH), 256, shmem>>>(pql, pk, pattn3);
    k_softmax4096<<<dim3(MM, BH), 256>>>(pattn3);
    // 6) pinv init
    k_zero_red<<<1, 1>>>(pred);
    k_pinv_prep<<<BH, 256>>>(pattn2, pred);
    k_zinit<<<8192, 256>>>(pattn2, pzA, pred);
    // 7) 6 Newton-Schulz-style iterations
    float* zp = pzA;
    float* z2p = pzB;
    for (int it = 0; it < 6; it++) {
        k_gemm256<<<dim3(4, 4, BH), 256>>>(pattn2, zp, pxz, 0.f, 1.f, 1.f);     // xz = x@z
        k_gemm256<<<dim3(4, 4, BH), 256>>>(pxz, pxz, pt, 7.f, -1.f, 1.f);       // t = 7xz - xz@xz
        k_gemm256<<<dim3(4, 4, BH), 256>>>(pxz, pt, pu, 15.f, -1.f, 1.f);       // u = 15xz - xz@t
        k_gemm256<<<dim3(4, 4, BH), 256>>>(zp, pu, z2p, 13.f, -1.f, 0.25f);     // z' = .25(13z - z@u)
        float* sw = zp; zp = z2p; z2p = sw;
    }
    // 8) tmp1 = attn3 @ v
    k_gemm_b64<<<dim3(4, BH), 256>>>(pattn3, (size_t)MM * NN, NN,
                                     pv, (size_t)NN * DH, ptmp1, (size_t)MM * DH, NN);
    // 9) tmp2 = z @ tmp1
    k_gemm_b64<<<dim3(4, BH), 256>>>(zp, (size_t)MM * MM, MM,
                                     ptmp1, (size_t)MM * DH, ptmp2, (size_t)MM * DH, MM);
    // 10) outh = attn1 @ tmp2 + conv residual
    k_outh<<<dim3(64, BH), 256>>>(pattn1, ptmp2, pv, wres, pouth);
    // 11) out = reshape(outh) @ w_out
    k_final<<<dim3(8, 256), 256>>>(pouth, wout, (float*)d_out);
}

// round 3
// speedup vs baseline: 1.4415x; 1.4415x over previous
#include <cuda_runtime.h>
#include <float.h>
#include <cstdint>
#include <mma.h>
using namespace nvcuda;

#define BB 4
#define NN 4096
#define DIMD 512
#define HH 8
#define DH 64
#define MM 256
#define LL 16
#define BH (BB*HH)          // 32

// ------------------- scratch (device globals; no allocs) -------------------
__device__ float g_q[BH*NN*DH];
__device__ float g_k[BH*NN*DH];
__device__ float g_v[BH*NN*DH];
__device__ float g_ql[BH*MM*DH];
__device__ float g_kl[BH*MM*DH];
__device__ float g_attn1[(size_t)BH*NN*MM];
__device__ float g_attn3[(size_t)BH*MM*NN];
__device__ float g_attn2[BH*MM*MM];
__device__ float g_zA[BH*MM*MM];
__device__ float g_zB[BH*MM*MM];
__device__ float g_xz[BH*MM*MM];
__device__ float g_t[BH*MM*MM];
__device__ float g_u[BH*MM*MM];
__device__ float g_tmp1[BH*MM*DH];
__device__ float g_tmp2[BH*MM*DH];
__device__ float g_outh[BH*NN*DH];
__device__ int   g_red[2];

// strides (floats) inside dynamic smem
#define AST 40      // A tile stride: [128][40]
#define BST 136     // B tile stride: [32][136]
#define SST 136     // staging stride: [128][136]
#define B64ST 72    // B tile stride for N=64 kernels

#define CVT_FRAG(f) do { for (int _t = 0; _t < (f).num_elements; _t++) (f).x[_t] = wmma::__float_to_tf32((f).x[_t]); } while (0)

// ================== mma kernel 1: qkv = X @ Wqkv, scatter ==================
__global__ void k_qkv_mma(const float* __restrict__ X, const float* __restrict__ W,
                          float* __restrict__ q, float* __restrict__ k, float* __restrict__ v)
{
    extern __shared__ float smf[];
    float* As = smf;
    float* Bs = As + 128 * AST;
    float* St = Bs + 32 * BST;
    int tid = threadIdx.x, wid = tid >> 5;
    int wm = wid >> 2, wn = wid & 3;               // 2x4 warps
    int row0 = blockIdx.y * 128, col0 = blockIdx.x * 128;

    wmma::fragment<wmma::accumulator, 16, 16, 8, float> acc[4][2];
#pragma unroll
    for (int mf = 0; mf < 4; mf++)
#pragma unroll
        for (int nf = 0; nf < 2; nf++) wmma::fill_fragment(acc[mf][nf], 0.f);

    for (int k0 = 0; k0 < 512; k0 += 32) {
        for (int i = tid; i < 1024; i += 256) {
            int r = i >> 3, f = i & 7;
            *(float4*)&As[r * AST + f * 4] = *(const float4*)&X[(size_t)(row0 + r) * 512 + k0 + f * 4];
        }
        for (int i = tid; i < 1024; i += 256) {
            int kk = i >> 5, c4 = i & 31;
            *(float4*)&Bs[kk * BST + c4 * 4] = *(const float4*)&W[(size_t)(k0 + kk) * 1536 + col0 + c4 * 4];
        }
        __syncthreads();
#pragma unroll
        for (int ks = 0; ks < 4; ks++) {
            wmma::fragment<wmma::matrix_b, 16, 16, 8, wmma::precision::tf32, wmma::row_major> bf[2];
#pragma unroll
            for (int nf = 0; nf < 2; nf++) {
                wmma::load_matrix_sync(bf[nf], Bs + (ks * 8) * BST + wn * 32 + nf * 16, BST);
                CVT_FRAG(bf[nf]);
            }
#pragma unroll
            for (int mf = 0; mf < 4; mf++) {
                wmma::fragment<wmma::matrix_a, 16, 16, 8, wmma::precision::tf32, wmma::row_major> af;
                wmma::load_matrix_sync(af, As + (wm * 64 + mf * 16) * AST + ks * 8, AST);
                CVT_FRAG(af);
#pragma unroll
                for (int nf = 0; nf < 2; nf++) wmma::mma_sync(acc[mf][nf], af, bf[nf], acc[mf][nf]);
            }
        }
        __syncthreads();
    }
#pragma unroll
    for (int mf = 0; mf < 4; mf++)
#pragma unroll
        for (int nf = 0; nf < 2; nf++)
            wmma::store_matrix_sync(St + (wm * 64 + mf * 16) * SST + wn * 32 + nf * 16,
                                    acc[mf][nf], SST, wmma::mem_row_major);
    __syncthreads();
    for (int i = tid; i < 128 * 32; i += 256) {
        int r = i >> 5, c = (i & 31) * 4;
        float4 val = *(float4*)&St[r * SST + c];
        int rg = row0 + r, b = rg >> 12, n = rg & 4095;
        int cg = col0 + c, which = cg >> 9, h = (cg & 511) >> 6, d = cg & 63;
        float* dst;
        if (which == 0) { val.x *= 0.125f; val.y *= 0.125f; val.z *= 0.125f; val.w *= 0.125f; dst = q; }
        else if (which == 1) dst = k;
        else dst = v;
        *(float4*)&dst[((size_t)(b * 8 + h) * 4096 + n) * 64 + d] = val;
    }
}

// ======== mma kernel 2: batched 256^3  C = scale*(coef*A + sgn*A@B) ========
__global__ void k_g256_mma(const float* __restrict__ A, const float* __restrict__ B,
                           float* __restrict__ C, float coef, float sgn, float scale)
{
    extern __shared__ float smf[];
    float* As = smf;
    float* Bs = As + 128 * AST;
    float* St = Bs + 32 * BST;
    int tid = threadIdx.x, wid = tid >> 5;
    int wm = wid >> 2, wn = wid & 3;
    size_t base = (size_t)blockIdx.z << 16;
    int row0 = blockIdx.y * 128, col0 = blockIdx.x * 128;

    wmma::fragment<wmma::accumulator, 16, 16, 8, float> acc[4][2];
#pragma unroll
    for (int mf = 0; mf < 4; mf++)
#pragma unroll
        for (int nf = 0; nf < 2; nf++) wmma::fill_fragment(acc[mf][nf], 0.f);

    for (int k0 = 0; k0 < 256; k0 += 32) {
        for (int i = tid; i < 1024; i += 256) {
            int r = i >> 3, f = i & 7;
            *(float4*)&As[r * AST + f * 4] = *(const float4*)&A[base + (size_t)(row0 + r) * 256 + k0 + f * 4];
        }
        for (int i = tid; i < 1024; i += 256) {
            int kk = i >> 5, c4 = i & 31;
            *(float4*)&Bs[kk * BST + c4 * 4] = *(const float4*)&B[base + (size_t)(k0 + kk) * 256 + col0 + c4 * 4];
        }
        __syncthreads();
#pragma unroll
        for (int ks = 0; ks < 4; ks++) {
            wmma::fragment<wmma::matrix_b, 16, 16, 8, wmma::precision::tf32, wmma::row_major> bf[2];
#pragma unroll
            for (int nf = 0; nf < 2; nf++) {
                wmma::load_matrix_sync(bf[nf], Bs + (ks * 8) * BST + wn * 32 + nf * 16, BST);
                CVT_FRAG(bf[nf]);
            }
#pragma unroll
            for (int mf = 0; mf < 4; mf++) {
                wmma::fragment<wmma::matrix_a, 16, 16, 8, wmma::precision::tf32, wmma::row_major> af;
                wmma::load_matrix_sync(af, As + (wm * 64 + mf * 16) * AST + ks * 8, AST);
                CVT_FRAG(af);
#pragma unroll
                for (int nf = 0; nf < 2; nf++) wmma::mma_sync(acc[mf][nf], af, bf[nf], acc[mf][nf]);
            }
        }
        __syncthreads();
    }
#pragma unroll
    for (int mf = 0; mf < 4; mf++)
#pragma unroll
        for (int nf = 0; nf < 2; nf++)
            wmma::store_matrix_sync(St + (wm * 64 + mf * 16) * SST + wn * 32 + nf * 16,
                                    acc[mf][nf], SST, wmma::mem_row_major);
    __syncthreads();
    for (int i = tid; i < 128 * 32; i += 256) {
        int r = i >> 5, c = (i & 31) * 4;
        float4 sv = *(float4*)&St[r * SST + c];
        size_t go = base + (size_t)(row0 + r) * 256 + col0 + c;
        float4 av = *(const float4*)&A[go];
        float4 st;
        st.x = scale * (sgn * sv.x + coef * av.x);
        st.y = scale * (sgn * sv.y + coef * av.y);
        st.z = scale * (sgn * sv.z + coef * av.z);
        st.w = scale * (sgn * sv.w + coef * av.w);
        *(float4*)&C[go] = st;
    }
}

// ====== mma kernel 3: batched C[rows x 64] = A[rows x K] @ B[K x 64] =======
__global__ void k_b64_mma(const float* __restrict__ A, size_t sA, int lda,
                          const float* __restrict__ B, size_t sB,
                          float* __restrict__ C, size_t sC, int K)
{
    extern __shared__ float smf[];
    float* As = smf;
    float* Bs = As + 128 * AST;
    int tid = threadIdx.x, wid = tid >> 5;
    int wm = wid >> 1, wn = wid & 1;               // 4x2 warps, warp tile 32x32
    int bh = blockIdx.y;
    int row0 = blockIdx.x * 128;
    const float* Ab = A + (size_t)bh * sA;
    const float* Bb = B + (size_t)bh * sB;
    float* Cb = C + (size_t)bh * sC;

    wmma::fragment<wmma::accumulator, 16, 16, 8, float> acc[2][2];
#pragma unroll
    for (int mf = 0; mf < 2; mf++)
#pragma unroll
        for (int nf = 0; nf < 2; nf++) wmma::fill_fragment(acc[mf][nf], 0.f);

    for (int k0 = 0; k0 < K; k0 += 32) {
        for (int i = tid; i < 1024; i += 256) {
            int r = i >> 3, f = i & 7;
            *(float4*)&As[r * AST + f * 4] = *(const float4*)&Ab[(size_t)(row0 + r) * lda + k0 + f * 4];
        }
        for (int i = tid; i < 512; i += 256) {
            int kk = i >> 4, c4 = i & 15;
            *(float4*)&Bs[kk * B64ST + c4 * 4] = *(const float4*)&Bb[(size_t)(k0 + kk) * 64 + c4 * 4];
        }
        __syncthreads();
#pragma unroll
        for (int ks = 0; ks < 4; ks++) {
            wmma::fragment<wmma::matrix_b, 16, 16, 8, wmma::precision::tf32, wmma::row_major> bf[2];
#pragma unroll
            for (int nf = 0; nf < 2; nf++) {
                wmma::load_matrix_sync(bf[nf], Bs + (ks * 8) * B64ST + wn * 32 + nf * 16, B64ST);
                CVT_FRAG(bf[nf]);
            }
#pragma unroll
            for (int mf = 0; mf < 2; mf++) {
                wmma::fragment<wmma::matrix_a, 16, 16, 8, wmma::precision::tf32, wmma::row_major> af;
                wmma::load_matrix_sync(af, As + (wm * 32 + mf * 16) * AST + ks * 8, AST);
                CVT_FRAG(af);
#pragma unroll
                for (int nf = 0; nf < 2; nf++) wmma::mma_sync(acc[mf][nf], af, bf[nf], acc[mf][nf]);
            }
        }
        __syncthreads();
    }
#pragma unroll
    for (int mf = 0; mf < 2; mf++)
#pragma unroll
        for (int nf = 0; nf < 2; nf++)
            wmma::store_matrix_sync(&Cb[(size_t)(row0 + wm * 32 + mf * 16) * 64 + wn * 32 + nf * 16],
                                    acc[mf][nf], 64, wmma::mem_row_major);
}

// ============ mma kernel 4: out = gather(outh) @ Wout (M=16384) ============
__global__ void k_final_mma(const float* __restrict__ outh, const float* __restrict__ W,
                            float* __restrict__ out)
{
    extern __shared__ float smf[];
    float* As = smf;
    float* Bs = As + 128 * AST;
    int tid = threadIdx.x, wid = tid >> 5;
    int wm = wid >> 2, wn = wid & 3;
    int row0 = blockIdx.y * 128, col0 = blockIdx.x * 128;

    wmma::fragment<wmma::accumulator, 16, 16, 8, float> acc[4][2];
#pragma unroll
    for (int mf = 0; mf < 4; mf++)
#pragma unroll
        for (int nf = 0; nf < 2; nf++) wmma::fill_fragment(acc[mf][nf], 0.f);

    for (int k0 = 0; k0 < 512; k0 += 32) {
        for (int i = tid; i < 1024; i += 256) {
            int r = i >> 3, f = i & 7;
            int rg = row0 + r;
            int b = rg >> 12, n = rg & 4095;
            int kg = k0 + f * 4;
            int h = kg >> 6, d = kg & 63;
            *(float4*)&As[r * AST + f * 4] =
                *(const float4*)&outh[((size_t)(b * 8 + h) * 4096 + n) * 64 + d];
        }
        for (int i = tid; i < 1024; i += 256) {
            int kk = i >> 5, c4 = i & 31;
            *(float4*)&Bs[kk * BST + c4 * 4] = *(const float4*)&W[(size_t)(k0 + kk) * 512 + col0 + c4 * 4];
        }
        __syncthreads();
#pragma unroll
        for (int ks = 0; ks < 4; ks++) {
            wmma::fragment<wmma::matrix_b, 16, 16, 8, wmma::precision::tf32, wmma::row_major> bf[2];
#pragma unroll
            for (int nf = 0; nf < 2; nf++) {
                wmma::load_matrix_sync(bf[nf], Bs + (ks * 8) * BST + wn * 32 + nf * 16, BST);
                CVT_FRAG(bf[nf]);
            }
#pragma unroll
            for (int mf = 0; mf < 4; mf++) {
                wmma::fragment<wmma::matrix_a, 16, 16, 8, wmma::precision::tf32, wmma::row_major> af;
                wmma::load_matrix_sync(af, As + (wm * 64 + mf * 16) * AST + ks * 8, AST);
                CVT_FRAG(af);
#pragma unroll
                for (int nf = 0; nf < 2; nf++) wmma::mma_sync(acc[mf][nf], af, bf[nf], acc[mf][nf]);
            }
        }
        __syncthreads();
    }
#pragma unroll
    for (int mf = 0; mf < 4; mf++)
#pragma unroll
        for (int nf = 0; nf < 2; nf++)
            wmma::store_matrix_sync(&out[(size_t)(row0 + wm * 64 + mf * 16) * 512 + col0 + wn * 32 + nf * 16],
                                    acc[mf][nf], 512, wmma::mem_row_major);
}

// ================== conv residual: outh += depthwise_conv(v) ===============
__global__ void k_conv(const float* __restrict__ v, const float* __restrict__ wres,
                       float* __restrict__ outh)
{
    __shared__ __align__(16) float vbuf[160 * 64];
    __shared__ float wc[33];
    int tid = threadIdx.x;
    int bh = blockIdx.y, h = bh & 7;
    int row0 = blockIdx.x * 128;
    if (tid < 33) wc[tid] = wres[h * 33 + tid];
    for (int i = tid; i < 160 * 64; i += 256) {
        int rr = i >> 6, d = i & 63;
        int n = row0 + rr - 16;
        vbuf[i] = (n >= 0 && n < NN) ? v[((size_t)bh * NN + n) * 64 + d] : 0.f;
    }
    __syncthreads();
    int tx = tid & 15, ty = tid >> 4;
#pragma unroll
    for (int rr = 0; rr < 8; rr++) {
        int rl = ty * 8 + rr;
        float4 cv = {0.f, 0.f, 0.f, 0.f};
#pragma unroll 1
        for (int t = 0; t < 33; t++) {
            float w = wc[t];
            float4 vb = *(const float4*)&vbuf[(rl + t) * 64 + tx * 4];
            cv.x += w * vb.x; cv.y += w * vb.y; cv.z += w * vb.z; cv.w += w * vb.w;
        }
        size_t o = ((size_t)bh * NN + row0 + rl) * 64 + tx * 4;
        float4 cur = *(const float4*)&outh[o];
        cur.x += cv.x; cur.y += cv.y; cur.z += cv.z; cur.w += cv.w;
        *(float4*)&outh[o] = cur;
    }
}

// ================= fp32 kernels (sims, softmax, pinv prep) =================
__global__ void k_land(const float* __restrict__ q, const float* __restrict__ k,
                       float* __restrict__ ql, float* __restrict__ kl)
{
    int idx = blockIdx.x * 256 + threadIdx.x;
    int d = idx & 63;
    int m = (idx >> 6) & 255;
    int bh = idx >> 14;
    size_t base = ((size_t)bh * NN + m * LL) * DH + d;
    float sq = 0.f, sk = 0.f;
#pragma unroll
    for (int i = 0; i < LL; i++) { sq += q[base + (size_t)i * DH]; sk += k[base + (size_t)i * DH]; }
    ql[idx] = sq * (1.f / LL);
    kl[idx] = sk * (1.f / LL);
}

__global__ void k_sim_softmax(const float* __restrict__ Q, const float* __restrict__ KL,
                              float* __restrict__ Out, int nrows)
{
    extern __shared__ float smf[];
    float* ks = smf;
    float* qs = smf + 256 * 65;
    int tid = threadIdx.x;
    int bh = blockIdx.y;
    int row0 = blockIdx.x * 64;
    const float* Qb = Q + ((size_t)bh * nrows + row0) * DH;
    const float* Kb = KL + (size_t)bh * MM * DH;
    for (int i = tid; i < 256 * 64; i += 256) { int c = i >> 6, d = i & 63; ks[c * 65 + d] = Kb[i]; }
    for (int i = tid; i < 64 * 64;  i += 256) { int r = i >> 6, d = i & 63; qs[r * 65 + d] = Qb[i]; }
    __syncthreads();
    int tx = tid & 31, ty = tid >> 5;
    int c1 = tx * 4, c2 = 128 + tx * 4;
    float acc[8][8] = {};
#pragma unroll 4
    for (int d = 0; d < 64; d++) {
        float a_[8];
#pragma unroll
        for (int i = 0; i < 8; i++) a_[i] = qs[(ty * 8 + i) * 65 + d];
        float b_[8];
#pragma unroll
        for (int j = 0; j < 4; j++) { b_[j] = ks[(c1 + j) * 65 + d]; b_[4 + j] = ks[(c2 + j) * 65 + d]; }
#pragma unroll
        for (int i = 0; i < 8; i++)
#pragma unroll
            for (int j = 0; j < 8; j++) acc[i][j] += a_[i] * b_[j];
    }
#pragma unroll
    for (int i = 0; i < 8; i++) {
        float m = acc[i][0];
#pragma unroll
        for (int j = 1; j < 8; j++) m = fmaxf(m, acc[i][j]);
        for (int o = 16; o > 0; o >>= 1) m = fmaxf(m, __shfl_xor_sync(0xffffffffu, m, o));
        float s = 0.f;
#pragma unroll
        for (int j = 0; j < 8; j++) { float e = expf(acc[i][j] - m); acc[i][j] = e; s += e; }
        for (int o = 16; o > 0; o >>= 1) s += __shfl_xor_sync(0xffffffffu, s, o);
        float inv = 1.f / s;
        float* orow = Out + ((size_t)bh * nrows + row0 + ty * 8 + i) * MM;
        float4 w1 = {acc[i][0] * inv, acc[i][1] * inv, acc[i][2] * inv, acc[i][3] * inv};
        float4 w2 = {acc[i][4] * inv, acc[i][5] * inv, acc[i][6] * inv, acc[i][7] * inv};
        *(float4*)(orow + c1) = w1;
        *(float4*)(orow + c2) = w2;
    }
}

__global__ void k_sim3(const float* __restrict__ QL, const float* __restrict__ K,
                       float* __restrict__ Out)
{
    extern __shared__ float smf[];
    float* ks = smf;
    float* qs = smf + 256 * 65;
    int tid = threadIdx.x;
    int bh = blockIdx.z;
    int row0 = blockIdx.y * 64;
    int col0 = blockIdx.x * 256;
    const float* Qb = QL + ((size_t)bh * MM + row0) * DH;
    const float* Kb = K + ((size_t)bh * NN + col0) * DH;
    for (int i = tid; i < 256 * 64; i += 256) { int c = i >> 6, d = i & 63; ks[c * 65 + d] = Kb[i]; }
    for (int i = tid; i < 64 * 64;  i += 256) { int r = i >> 6, d = i & 63; qs[r * 65 + d] = Qb[i]; }
    __syncthreads();
    int tx = tid & 31, ty = tid >> 5;
    int c1 = tx * 4, c2 = 128 + tx * 4;
    float acc[8][8] = {};
#pragma unroll 4
    for (int d = 0; d < 64; d++) {
        float a_[8];
#pragma unroll
        for (int i = 0; i < 8; i++) a_[i] = qs[(ty * 8 + i) * 65 + d];
        float b_[8];
#pragma unroll
        for (int j = 0; j < 4; j++) { b_[j] = ks[(c1 + j) * 65 + d]; b_[4 + j] = ks[(c2 + j) * 65 + d]; }
#pragma unroll
        for (int i = 0; i < 8; i++)
#pragma unroll
            for (int j = 0; j < 8; j++) acc[i][j] += a_[i] * b_[j];
    }
#pragma unroll
    for (int i = 0; i < 8; i++) {
        float* orow = Out + ((size_t)bh * MM + row0 + ty * 8 + i) * NN + col0;
        float4 w1 = {acc[i][0], acc[i][1], acc[i][2], acc[i][3]};
        float4 w2 = {acc[i][4], acc[i][5], acc[i][6], acc[i][7]};
        *(float4*)(orow + c1) = w1;
        *(float4*)(orow + c2) = w2;
    }
}

__global__ void k_softmax4096(float* __restrict__ A)
{
    __shared__ float smax[32];
    __shared__ float ssum[32];
    int tid = threadIdx.x;
    int wid = tid >> 5, lane = tid & 31;
    float4* row = (float4*)(A + ((size_t)blockIdx.y * MM + blockIdx.x) * NN);
    float4 vals[4];
    float m = -FLT_MAX;
#pragma unroll
    for (int kk = 0; kk < 4; kk++) {
        vals[kk] = row[tid + 256 * kk];
        m = fmaxf(m, fmaxf(fmaxf(vals[kk].x, vals[kk].y), fmaxf(vals[kk].z, vals[kk].w)));
    }
    for (int o = 16; o > 0; o >>= 1) m = fmaxf(m, __shfl_xor_sync(0xffffffffu, m, o));
    if (lane == 0) smax[wid] = m;
    __syncthreads();
    if (wid == 0) {
        float v = (lane < 8) ? smax[lane] : -FLT_MAX;
        for (int o = 16; o > 0; o >>= 1) v = fmaxf(v, __shfl_xor_sync(0xffffffffu, v, o));
        if (lane == 0) smax[0] = v;
    }
    __syncthreads();
    m = smax[0];
    float s = 0.f;
#pragma unroll
    for (int kk = 0; kk < 4; kk++) {
        vals[kk].x = expf(vals[kk].x - m); vals[kk].y = expf(vals[kk].y - m);
        vals[kk].z = expf(vals[kk].z - m); vals[kk].w = expf(vals[kk].w - m);
        s += vals[kk].x + vals[kk].y + vals[kk].z + vals[kk].w;
    }
    for (int o = 16; o > 0; o >>= 1) s += __shfl_xor_sync(0xffffffffu, s, o);
    if (lane == 0) ssum[wid] = s;
    __syncthreads();
    if (wid == 0) {
        float v = (lane < 8) ? ssum[lane] : 0.f;
        for (int o = 16; o > 0; o >>= 1) v += __shfl_xor_sync(0xffffffffu, v, o);
        if (lane == 0) ssum[0] = v;
    }
    __syncthreads();
    float inv = 1.f / ssum[0];
#pragma unroll
    for (int kk = 0; kk < 4; kk++) {
        vals[kk].x *= inv; vals[kk].y *= inv; vals[kk].z *= inv; vals[kk].w *= inv;
        row[tid + 256 * kk] = vals[kk];
    }
}

__global__ void k_zero_red(int* red) { red[0] = 0; red[1] = 0; }

__global__ void k_pinv_prep(const float* __restrict__ X, int* red)
{
    __shared__ float s1[32], s2[32];
    int bh = blockIdx.x;
    int j = threadIdx.x;
    int wid = j >> 5, lane = j & 31;
    const float* Xb = X + (size_t)bh * MM * MM;
    float cs = 0.f, rs = 0.f;
    for (int i = 0; i < MM; i++) { cs += fabsf(Xb[j * MM + i]); rs += fabsf(Xb[i * MM + j]); }
    for (int o = 16; o > 0; o >>= 1) {
        cs = fmaxf(cs, __shfl_xor_sync(0xffffffffu, cs, o));
        rs = fmaxf(rs, __shfl_xor_sync(0xffffffffu, rs, o));
    }
    if (lane == 0) { s1[wid] = cs; s2[wid] = rs; }
    __syncthreads();
    if (wid == 0) {
        float a = (lane < 8) ? s1[lane] : 0.f;
        float b = (lane < 8) ? s2[lane] : 0.f;
        for (int o = 16; o > 0; o >>= 1) {
            a = fmaxf(a, __shfl_xor_sync(0xffffffffu, a, o));
            b = fmaxf(b, __shfl_xor_sync(0xffffffffu, b, o));
        }
        if (lane == 0) {
            atomicMax(&red[0], __float_as_int(a));
            atomicMax(&red[1], __float_as_int(b));
        }
    }
}

__global__ void k_zinit(const float* __restrict__ X, float* __restrict__ Z, const int* red)
{
    float denom = __int_as_float(red[0]) * __int_as_float(red[1]) + 1e-8f;
    int idx = blockIdx.x * 256 + threadIdx.x;
    int bh = idx >> 16;
    int rem = idx & 65535;
    int i = rem >> 8, j = rem & 255;
    Z[idx] = X[((size_t)bh << 16) + j * MM + i] / denom;
}

// --------------------------- host launcher --------------------------------
extern "C" void kernel_launch(void* const* d_in, const int* in_sizes, int n_in,
                              void* d_out, int out_size)
{
    const float *x = nullptr, *wqkv = nullptr, *wout = nullptr, *wres = nullptr;
    for (int i = 0; i < n_in; i++) {
        switch (in_sizes[i]) {
            case 8388608: x = (const float*)d_in[i]; break;
            case 786432:  wqkv = (const float*)d_in[i]; break;
            case 262144:  wout = (const float*)d_in[i]; break;
            case 264:     wres = (const float*)d_in[i]; break;
            default: break;
        }
    }

    float *pq, *pk, *pv, *pql, *pkl, *pattn1, *pattn3, *pattn2;
    float *pzA, *pzB, *pxz, *pt, *pu, *ptmp1, *ptmp2, *pouth;
    int* pred;
    cudaGetSymbolAddress((void**)&pq, g_q);
    cudaGetSymbolAddress((void**)&pk, g_k);
    cudaGetSymbolAddress((void**)&pv, g_v);
    cudaGetSymbolAddress((void**)&pql, g_ql);
    cudaGetSymbolAddress((void**)&pkl, g_kl);
    cudaGetSymbolAddress((void**)&pattn1, g_attn1);
    cudaGetSymbolAddress((void**)&pattn3, g_attn3);
    cudaGetSymbolAddress((void**)&pattn2, g_attn2);
    cudaGetSymbolAddress((void**)&pzA, g_zA);
    cudaGetSymbolAddress((void**)&pzB, g_zB);
    cudaGetSymbolAddress((void**)&pxz, g_xz);
    cudaGetSymbolAddress((void**)&pt, g_t);
    cudaGetSymbolAddress((void**)&pu, g_u);
    cudaGetSymbolAddress((void**)&ptmp1, g_tmp1);
    cudaGetSymbolAddress((void**)&ptmp2, g_tmp2);
    cudaGetSymbolAddress((void**)&pouth, g_outh);
    cudaGetSymbolAddress((void**)&pred, g_red);

    size_t shmem_sim = (size_t)(256 + 64) * 65 * sizeof(float);                     // 83200
    const int SM_BIG = (128 * AST + 32 * BST + 128 * SST) * sizeof(float);          // 107520
    const int SM_FIN = (128 * AST + 32 * BST) * sizeof(float);                      // 37888
    const int SM_B64 = (128 * AST + 32 * B64ST) * sizeof(float);                    // 29696
    cudaFuncSetAttribute(k_sim_softmax, cudaFuncAttributeMaxDynamicSharedMemorySize, (int)shmem_sim);
    cudaFuncSetAttribute(k_sim3, cudaFuncAttributeMaxDynamicSharedMemorySize, (int)shmem_sim);
    cudaFuncSetAttribute(k_qkv_mma, cudaFuncAttributeMaxDynamicSharedMemorySize, SM_BIG);
    cudaFuncSetAttribute(k_g256_mma, cudaFuncAttributeMaxDynamicSharedMemorySize, SM_BIG);
    cudaFuncSetAttribute(k_final_mma, cudaFuncAttributeMaxDynamicSharedMemorySize, SM_FIN);
    cudaFuncSetAttribute(k_b64_mma, cudaFuncAttributeMaxDynamicSharedMemorySize, SM_B64);

    // 1) qkv projection + head scatter (tensor cores, tf32)
    k_qkv_mma<<<dim3(12, 128), 256, SM_BIG>>>(x, wqkv, pq, pk, pv);
    // 2) landmarks
    k_land<<<2048, 256>>>(pq, pk, pql, pkl);
    // 3) sim1 + softmax : [bh,4096,256]
    k_sim_softmax<<<dim3(64, BH), 256, shmem_sim>>>(pq, pkl, pattn1, NN);
    // 4) sim2 + softmax : [bh,256,256]
    k_sim_softmax<<<dim3(4, BH), 256, shmem_sim>>>(pql, pkl, pattn2, MM);
    // 5) sim3 raw + softmax over 4096
    k_sim3<<<dim3(16, 4, BH), 256, shmem_sim>>>(pql, pk, pattn3);
    k_softmax4096<<<dim3(MM, BH), 256>>>(pattn3);
    // 6) pinv init
    k_zero_red<<<1, 1>>>(pred);
    k_pinv_prep<<<BH, 256>>>(pattn2, pred);
    k_zinit<<<8192, 256>>>(pattn2, pzA, pred);
    // 7) 6 Newton-Schulz iterations on tensor cores
    float* zp = pzA;
    float* z2p = pzB;
    for (int it = 0; it < 6; it++) {
        k_g256_mma<<<dim3(2, 2, BH), 256, SM_BIG>>>(pattn2, zp, pxz, 0.f, 1.f, 1.f);
        k_g256_mma<<<dim3(2, 2, BH), 256, SM_BIG>>>(pxz, pxz, pt, 7.f, -1.f, 1.f);
        k_g256_mma<<<dim3(2, 2, BH), 256, SM_BIG>>>(pxz, pt, pu, 15.f, -1.f, 1.f);
        k_g256_mma<<<dim3(2, 2, BH), 256, SM_BIG>>>(zp, pu, z2p, 13.f, -1.f, 0.25f);
        float* sw = zp; zp = z2p; z2p = sw;
    }
    // 8) tmp1 = attn3 @ v   (K = 4096)
    k_b64_mma<<<dim3(2, BH), 256, SM_B64>>>(pattn3, (size_t)MM * NN, NN,
                                            pv, (size_t)NN * DH, ptmp1, (size_t)MM * DH, NN);
    // 9) tmp2 = z @ tmp1    (K = 256)
    k_b64_mma<<<dim3(2, BH), 256, SM_B64>>>(zp, (size_t)MM * MM, MM,
                                            ptmp1, (size_t)MM * DH, ptmp2, (size_t)MM * DH, MM);
    // 10) outh = attn1 @ tmp2 (K = 256), then add conv residual
    k_b64_mma<<<dim3(32, BH), 256, SM_B64>>>(pattn1, (size_t)NN * MM, MM,
                                             ptmp2, (size_t)MM * DH, pouth, (size_t)NN * DH, MM);
    k_conv<<<dim3(32, BH), 256>>>(pv, wres, pouth);
    // 11) out = reshape(outh) @ w_out (tensor cores, tf32)
    k_final_mma<<<dim3(4, 128), 256, SM_FIN>>>(pouth, wout, (float*)d_out);
}